// round 7
// baseline (speedup 1.0000x reference)
#include <cuda_runtime.h>
#include <cstddef>

#define NMAT 32768
#define CDIM 128
#define NDIM 64
#define MATSZ 4096  // 64*64

// Scratch (static device arrays: the sanctioned alloc-free workaround)
__device__ float g_logX[(size_t)NMAT * MATSZ];   // 512 MB
__device__ float g_logP[CDIM * MATSZ];           // 2 MB
__device__ float g_B[MATSZ * CDIM];              // A_sym, k-major for GEMM (2 MB)
__device__ float g_q[CDIM];                      // tr(logP_c * A_sym_c)

// ---------------------------------------------------------------------------
// Build B[k][c] = A_sym_c[i][j], k = i*64+j, where A_sym = tril(A,-1)+tril^T+diag
// ---------------------------------------------------------------------------
__global__ void prep_b_kernel(const float* __restrict__ A) {
    int lin = blockIdx.x * blockDim.x + threadIdx.x;   // 0 .. 4096*128-1
    int c = lin & (CDIM - 1);
    int k = lin >> 7;
    int i = k >> 6, j = k & 63;
    float v;
    if (i == j)      v = A[(size_t)c * MATSZ + i * 64 + i];
    else if (i > j)  v = A[(size_t)c * MATSZ + i * 64 + j];
    else             v = A[(size_t)c * MATSZ + j * 64 + i];
    g_B[(size_t)k * CDIM + c] = v;
}

// ---------------------------------------------------------------------------
// Batched Jacobi eigensolver + logm. One CTA (256 threads) per 64x64 SPD matrix.
// Positional circle-method tournament: seats live in warp-0 registers and are
// permuted by the fixed ring rotation each round; pair t = (seat[2t], seat[2t+1]).
// A: symmetric-half smem updates (warps 0-5).  V: REGISTER-RESIDENT on warps
// 6-7 (each owns a 32-row slice of the two V-columns at seats 2t/2t+1), columns
// migrate along the ring via shuffles. Demmel-Veselic relative threshold;
// converged when a full sweep applies no rotation.
// ---------------------------------------------------------------------------
__global__ __launch_bounds__(256, 2) void jacobi_logm_kernel(
    const float* __restrict__ src, float* __restrict__ dst) {
    __shared__ float sA[64][65];
    __shared__ float sV[64][65];
    __shared__ float2 scs[32];          // (c, s) per pair slot
    __shared__ int    spq[32];          // (p<<8)|q per pair slot (logical idx)
    __shared__ unsigned short sblk[496];// (bi<<8)|bj, bi<bj
    __shared__ float sl[64];
    __shared__ int   sseat[64];
    __shared__ unsigned sskip;          // bit t = slot t rotated this round
    __shared__ int sAny;

    const int tid  = threadIdx.x;
    const int lane = tid & 31;
    const int w    = tid >> 5;
    const float* Xm = src + (size_t)blockIdx.x * MATSZ;

    // Off-diagonal slot-pair table (once per CTA)
    for (int l = tid; l < 496; l += 256) {
        float f = (63.0f - sqrtf((float)(3969 - 8 * l))) * 0.5f;
        int bi = (int)f;
        if (bi > 30) bi = 30;
        while ((63 * bi - bi * bi) / 2 > l) bi--;
        while ((63 * (bi + 1) - (bi + 1) * (bi + 1)) / 2 <= l) bi++;
        int off = (63 * bi - bi * bi) / 2;
        int bj = bi + 1 + (l - off);
        sblk[l] = (unsigned short)((bi << 8) | bj);
    }

    // Load A into smem
    #pragma unroll
    for (int t = 0; t < 16; t++) {
        int idx = tid + t * 256;
        sA[idx >> 6][idx & 63] = Xm[idx];
    }

    // Seats (warp 0 registers): identity
    int s_top = 2 * lane, s_bot = 2 * lane + 1;

    // V register slices (warps 6,7): V = I.  Warp 6 rows 0-31, warp 7 rows 32-63.
    float v0[32], v1[32];
    const int rbase = (w == 7) ? 32 : 0;
    if (w >= 6) {
        #pragma unroll
        for (int k = 0; k < 32; k++) {
            int grow = rbase + k;
            v0[k] = (grow == 2 * lane) ? 1.0f : 0.0f;
            v1[k] = (grow == 2 * lane + 1) ? 1.0f : 0.0f;
        }
    }
    __syncthreads();

    const float eps2 = 4e-14f;   // (2e-7)^2 relative rotation threshold

    for (int sweep = 0; sweep < 12; sweep++) {
        if (tid == 0) sAny = 0;
        __syncthreads();
        for (int r = 0; r < 63; r++) {
            // --- phase 1 (warp 0): rotation params + diag update + seat perm ---
            if (w == 0) {
                int p = s_top, q = s_bot;
                float app = sA[p][p], aqq = sA[q][q];
                float apq = (p < q) ? sA[p][q] : sA[q][p];
                bool rot = (apq * apq > eps2 * app * aqq);
                float cc = 1.0f, sn = 0.0f;
                if (rot) {
                    float tau = (aqq - app) / (2.0f * apq);
                    float t = copysignf(1.0f, tau) /
                              (fabsf(tau) + sqrtf(1.0f + tau * tau));
                    cc = rsqrtf(1.0f + t * t);
                    sn = t * cc;
                    sA[p][p] = app - t * apq;
                    sA[q][q] = aqq + t * apq;
                    if (p < q) sA[p][q] = 0.0f; else sA[q][p] = 0.0f;
                }
                spq[lane] = (p << 8) | q;
                scs[lane] = make_float2(cc, sn);
                unsigned msk = __ballot_sync(0xffffffffu, rot);
                if (lane == 0) { sskip = msk; if (msk) sAny = 1; }
                // circle-method seat rotation (ring): top shifts right, bottom left
                int up = __shfl_up_sync(0xffffffffu, s_top, 1);
                int dn = __shfl_down_sync(0xffffffffu, s_bot, 1);
                int b0 = __shfl_sync(0xffffffffu, s_bot, 0);
                int old_top = s_top;
                s_top = (lane == 0) ? s_top : ((lane == 1) ? b0 : up);
                s_bot = (lane == 31) ? old_top : dn;
            }
            __syncthreads();

            unsigned m = sskip;
            if (m) {
                if (w < 6) {
                    // --- A off-diagonal blocks (symmetric half), warps 0-5 ---
                    #pragma unroll
                    for (int t = 0; t < 3; t++) {
                        int blk = tid + t * 192;
                        if (blk < 496) {
                            int bb = sblk[blk];
                            int bi = bb >> 8, bj = bb & 255;
                            if (((m >> bi) | (m >> bj)) & 1u) {
                                int pqi = spq[bi], pqj = spq[bj];
                                int pi = pqi >> 8, qi = pqi & 255;
                                int pj = pqj >> 8, qj = pqj & 255;
                                float2 gi = scs[bi], gj = scs[bj];
                                float a  = (pi < pj) ? sA[pi][pj] : sA[pj][pi];
                                float b  = (pi < qj) ? sA[pi][qj] : sA[qj][pi];
                                float c2 = (qi < pj) ? sA[qi][pj] : sA[pj][qi];
                                float d  = (qi < qj) ? sA[qi][qj] : sA[qj][qi];
                                float a1 = gj.x * a  - gj.y * b;
                                float b1 = gj.y * a  + gj.x * b;
                                float c1 = gj.x * c2 - gj.y * d;
                                float d1 = gj.y * c2 + gj.x * d;
                                float na = gi.x * a1 - gi.y * c1;
                                float nc = gi.y * a1 + gi.x * c1;
                                float nb = gi.x * b1 - gi.y * d1;
                                float nd = gi.y * b1 + gi.x * d1;
                                if (pi < pj) sA[pi][pj] = na; else sA[pj][pi] = na;
                                if (qi < pj) sA[qi][pj] = nc; else sA[pj][qi] = nc;
                                if (pi < qj) sA[pi][qj] = nb; else sA[qj][pi] = nb;
                                if (qi < qj) sA[qi][qj] = nd; else sA[qj][qi] = nd;
                            }
                        }
                    }
                } else {
                    // --- V rotation (register-resident): slot = lane ---
                    if ((m >> lane) & 1u) {
                        float2 cs = scs[lane];
                        #pragma unroll
                        for (int k = 0; k < 32; k++) {
                            float x = v0[k], y = v1[k];
                            v0[k] = cs.x * x - cs.y * y;
                            v1[k] = cs.y * x + cs.x * y;
                        }
                    }
                }
            }
            // --- V column migration along the ring (ALWAYS, mirrors seat perm) ---
            if (w >= 6) {
                #pragma unroll
                for (int k = 0; k < 32; k++) {
                    float x0 = v0[k], x1 = v1[k];
                    float up = __shfl_up_sync(0xffffffffu, x0, 1);
                    float dn = __shfl_down_sync(0xffffffffu, x1, 1);
                    float b0 = __shfl_sync(0xffffffffu, x1, 0);
                    v0[k] = (lane == 0) ? x0 : ((lane == 1) ? b0 : up);
                    v1[k] = (lane == 31) ? x0 : dn;
                }
            }
            __syncthreads();
        }
        int any = sAny;
        __syncthreads();
        if (!any) break;
    }

    // Dump V registers and seat map to smem
    if (w >= 6) {
        #pragma unroll
        for (int k = 0; k < 32; k++) {
            sV[rbase + k][2 * lane]     = v0[k];
            sV[rbase + k][2 * lane + 1] = v1[k];
        }
    }
    if (w == 0) { sseat[2 * lane] = s_top; sseat[2 * lane + 1] = s_bot; }
    __syncthreads();

    // log of eigenvalues: V-slot s corresponds to logical index seat[s]
    if (tid < 64) {
        int l = sseat[tid];
        sl[tid] = logf(fmaxf(sA[l][l], 1e-12f));
    }
    __syncthreads();

    // logm = V * diag(log lambda) * V^T, 4x4 register tile per thread
    {
        int i0 = (tid >> 4) << 2;
        int j0 = (tid & 15) << 2;
        float acc[4][4];
        #pragma unroll
        for (int i = 0; i < 4; i++)
            #pragma unroll
            for (int j = 0; j < 4; j++) acc[i][j] = 0.0f;
        for (int k = 0; k < 64; k++) {
            float lk = sl[k];
            float ra0 = sV[i0 + 0][k], ra1 = sV[i0 + 1][k];
            float ra2 = sV[i0 + 2][k], ra3 = sV[i0 + 3][k];
            float rb0 = sV[j0 + 0][k] * lk, rb1 = sV[j0 + 1][k] * lk;
            float rb2 = sV[j0 + 2][k] * lk, rb3 = sV[j0 + 3][k] * lk;
            acc[0][0] += ra0 * rb0; acc[0][1] += ra0 * rb1;
            acc[0][2] += ra0 * rb2; acc[0][3] += ra0 * rb3;
            acc[1][0] += ra1 * rb0; acc[1][1] += ra1 * rb1;
            acc[1][2] += ra1 * rb2; acc[1][3] += ra1 * rb3;
            acc[2][0] += ra2 * rb0; acc[2][1] += ra2 * rb1;
            acc[2][2] += ra2 * rb2; acc[2][3] += ra2 * rb3;
            acc[3][0] += ra3 * rb0; acc[3][1] += ra3 * rb1;
            acc[3][2] += ra3 * rb2; acc[3][3] += ra3 * rb3;
        }
        float* out = dst + (size_t)blockIdx.x * MATSZ;
        #pragma unroll
        for (int i = 0; i < 4; i++) {
            float4 v = make_float4(acc[i][0], acc[i][1], acc[i][2], acc[i][3]);
            *(float4*)(out + (i0 + i) * 64 + j0) = v;
        }
    }
}

// ---------------------------------------------------------------------------
// q[c] = tr(logP_c * A_sym_c) = sum_k logP[c][k] * B[k][c]
// ---------------------------------------------------------------------------
__global__ void compute_q_kernel() {
    int c = blockIdx.x;
    int tid = threadIdx.x;
    __shared__ float sred[256];
    float acc = 0.0f;
    for (int k = tid; k < MATSZ; k += 256)
        acc += g_logP[(size_t)c * MATSZ + k] * g_B[(size_t)k * CDIM + c];
    sred[tid] = acc;
    __syncthreads();
    for (int o = 128; o > 0; o >>= 1) {
        if (tid < o) sred[tid] += sred[tid + o];
        __syncthreads();
    }
    if (tid == 0) g_q[c] = sred[0];
}

// ---------------------------------------------------------------------------
// SGEMM: out[M x 128] = logX[M x 4096] @ B[4096 x 128] - q[c]
// BM=64, BN=128, BK=16, TM=TN=8, 128 threads.
// ---------------------------------------------------------------------------
#define BM 64
#define BN 128
#define BK 16
__global__ __launch_bounds__(128) void gemm_kernel(
    const float* __restrict__ Amat, float* __restrict__ out) {
    __shared__ float As[BK][BM];   // transposed A tile
    __shared__ float Bs[BK][BN];
    __shared__ float sqv[BN];

    int tid = threadIdx.x;
    int rowg = tid >> 4;    // 0..7
    int colg = tid & 15;    // 0..15
    size_t row0 = (size_t)blockIdx.x * BM;

    if (tid < BN) sqv[tid] = g_q[tid];

    float acc[8][8];
    #pragma unroll
    for (int i = 0; i < 8; i++)
        #pragma unroll
        for (int j = 0; j < 8; j++) acc[i][j] = 0.0f;

    for (int kt = 0; kt < MATSZ; kt += BK) {
        #pragma unroll
        for (int l = 0; l < 2; l++) {
            int lin = tid + l * 128;
            int r = lin >> 2;
            int k4 = (lin & 3) * 4;
            float4 v = *(const float4*)(Amat + (row0 + r) * MATSZ + kt + k4);
            As[k4 + 0][r] = v.x; As[k4 + 1][r] = v.y;
            As[k4 + 2][r] = v.z; As[k4 + 3][r] = v.w;
        }
        #pragma unroll
        for (int l = 0; l < 4; l++) {
            int lin = tid + l * 128;
            int r = lin >> 5;
            int c4 = (lin & 31) * 4;
            *(float4*)&Bs[r][c4] =
                *(const float4*)(g_B + (size_t)(kt + r) * CDIM + c4);
        }
        __syncthreads();
        #pragma unroll
        for (int k = 0; k < BK; k++) {
            float ra[8], rb[8];
            #pragma unroll
            for (int i = 0; i < 8; i++) ra[i] = As[k][rowg * 8 + i];
            #pragma unroll
            for (int j = 0; j < 8; j++) rb[j] = Bs[k][colg * 8 + j];
            #pragma unroll
            for (int i = 0; i < 8; i++)
                #pragma unroll
                for (int j = 0; j < 8; j++)
                    acc[i][j] += ra[i] * rb[j];
        }
        __syncthreads();
    }
    #pragma unroll
    for (int i = 0; i < 8; i++) {
        size_t rr = row0 + rowg * 8 + i;
        #pragma unroll
        for (int j = 0; j < 8; j++) {
            int cc = colg * 8 + j;
            out[rr * CDIM + cc] = acc[i][j] - sqv[cc];
        }
    }
}

// ---------------------------------------------------------------------------
extern "C" void kernel_launch(void* const* d_in, const int* in_sizes, int n_in,
                              void* d_out, int out_size) {
    const float* X = (const float*)d_in[0];   // (32768, 64, 64)
    const float* P = (const float*)d_in[1];   // (128, 64, 64)
    const float* A = (const float*)d_in[2];   // (128, 64, 64)
    float* out = (float*)d_out;               // (32768, 128)

    float *p_logX, *p_logP;
    cudaGetSymbolAddress((void**)&p_logX, g_logX);
    cudaGetSymbolAddress((void**)&p_logP, g_logP);

    prep_b_kernel<<<(MATSZ * CDIM) / 256, 256>>>(A);
    jacobi_logm_kernel<<<CDIM, 256>>>(P, p_logP);
    compute_q_kernel<<<CDIM, 256>>>();
    jacobi_logm_kernel<<<NMAT, 256>>>(X, p_logX);
    gemm_kernel<<<NMAT / BM, 128>>>(p_logX, out);
}

// round 12
// speedup vs baseline: 1.5597x; 1.5597x over previous
#include <cuda_runtime.h>
#include <cstddef>

#define NMAT 32768
#define CDIM 128
#define NDIM 64
#define MATSZ 4096  // 64*64

// Scratch (static device arrays: the sanctioned alloc-free workaround)
__device__ float g_logX[(size_t)NMAT * MATSZ];   // 512 MB
__device__ float g_logP[CDIM * MATSZ];           // 2 MB
__device__ float g_B[MATSZ * CDIM];              // A_sym, k-major for GEMM (2 MB)
__device__ float g_q[CDIM];                      // tr(logP_c * A_sym_c)

// ---------------------------------------------------------------------------
// Build B[k][c] = A_sym_c[i][j], k = i*64+j, where A_sym = tril(A,-1)+tril^T+diag
// ---------------------------------------------------------------------------
__global__ void prep_b_kernel(const float* __restrict__ A) {
    int lin = blockIdx.x * blockDim.x + threadIdx.x;   // 0 .. 4096*128-1
    int c = lin & (CDIM - 1);
    int k = lin >> 7;
    int i = k >> 6, j = k & 63;
    float v;
    if (i == j)      v = A[(size_t)c * MATSZ + i * 64 + i];
    else if (i > j)  v = A[(size_t)c * MATSZ + i * 64 + j];
    else             v = A[(size_t)c * MATSZ + j * 64 + i];
    g_B[(size_t)k * CDIM + c] = v;
}

// remove bit b from p (inverse of insert-zero-at-b)
__device__ __forceinline__ int slot_of(int p, int b) {
    int mb = 1 << b;
    return (p & (mb - 1)) | ((p >> 1) & ~(mb - 1));
}
__device__ __forceinline__ void rot2(float& x, float& y, float c, float s) {
    float nx = c * x - s * y;
    y = s * x + c * y;
    x = nx;
}

// ---------------------------------------------------------------------------
// Batched Jacobi eigensolver + logm. One CTA (256 threads) per 64x64 SPD matrix.
// XOR tournament: round mask m pairs x <-> x^m; 63 masks = GF(64)* via LFSR,
// grouped into 21 XOR-closed triples {m1, m2, m1^m2} (GF(4)* cosets). V is
// updated once per 3 rounds: each 4-column coset of {0,m1,m2,m3} is closed
// under all three pairings, so a thread loads 4 V entries, applies all 6
// rotations in registers, stores once -> 3x less V smem traffic.
// A: symmetric-half (canonical upper) smem updates each round.
// Demmel-Veselic relative threshold; converged when a sweep does no rotation.
// ---------------------------------------------------------------------------
__global__ __launch_bounds__(256, 3) void jacobi_logm_kernel(
    const float* __restrict__ src, float* __restrict__ dst) {
    __shared__ float sA[64][65];
    __shared__ float sV[64][65];
    __shared__ float2 shist[3][32];     // (c,s) per round-in-group, per slot
    __shared__ int    spq[32];          // (p<<8)|q per slot (current round)
    __shared__ unsigned short sblk[496];// (bi<<8)|bj, bi<bj
    __shared__ unsigned char spow[63];  // GF(64)* powers of x (LFSR)
    __shared__ int sreps[16];           // coset minima for current group
    __shared__ unsigned smask[3];       // rotation-active mask per round
    __shared__ float sl[64];
    __shared__ int sAny;

    const int tid  = threadIdx.x;
    const int lane = tid & 31;
    const int w    = tid >> 5;
    const float* Xm = src + (size_t)blockIdx.x * MATSZ;

    // GF(64) power table: x^6 = x + 1 (primitive poly 0x43)
    if (tid == 0) {
        unsigned v = 1;
        for (int i = 0; i < 63; i++) {
            spow[i] = (unsigned char)v;
            v <<= 1;
            if (v & 64) v ^= 0x43;
        }
    }
    // Off-diagonal slot-pair table
    for (int l = tid; l < 496; l += 256) {
        float f = (63.0f - sqrtf((float)(3969 - 8 * l))) * 0.5f;
        int bi = (int)f;
        if (bi > 30) bi = 30;
        while ((63 * bi - bi * bi) / 2 > l) bi--;
        while ((63 * (bi + 1) - (bi + 1) * (bi + 1)) / 2 <= l) bi++;
        int off = (63 * bi - bi * bi) / 2;
        int bj = bi + 1 + (l - off);
        sblk[l] = (unsigned short)((bi << 8) | bj);
    }
    // Load A, init V = I
    #pragma unroll
    for (int t = 0; t < 16; t++) {
        int idx = tid + t * 256;
        int r = idx >> 6, c = idx & 63;
        sA[r][c] = Xm[idx];
        sV[r][c] = (r == c) ? 1.0f : 0.0f;
    }
    __syncthreads();

    const float eps2 = 4e-14f;   // (2e-7)^2 relative rotation threshold

    for (int sweep = 0; sweep < 14; sweep++) {
        if (tid == 0) sAny = 0;
        __syncthreads();
        for (int grp = 0; grp < 21; grp++) {
            const int m1 = spow[grp], m2 = spow[grp + 21], m3 = spow[grp + 42];
            #pragma unroll
            for (int j = 0; j < 3; j++) {
                const int m = (j == 0) ? m1 : ((j == 1) ? m2 : m3);
                const int b = 31 - __clz(m);
                // --- phase 1 (warp 0): rotation params + diag; warp 1: reps ---
                if (w == 0) {
                    int low = lane & ((1 << b) - 1);
                    int p = ((lane >> b) << (b + 1)) | low;
                    int q = p ^ m;                     // p < q (bit b of p is 0)
                    float app = sA[p][p], aqq = sA[q][q], apq = sA[p][q];
                    bool rot = (apq * apq > eps2 * app * aqq);
                    float cc = 1.0f, sn = 0.0f;
                    if (rot) {
                        float tau = (aqq - app) / (2.0f * apq);
                        float t = copysignf(1.0f, tau) /
                                  (fabsf(tau) + sqrtf(1.0f + tau * tau));
                        cc = rsqrtf(1.0f + t * t);
                        sn = t * cc;
                        sA[p][p] = app - t * apq;
                        sA[q][q] = aqq + t * apq;
                        sA[p][q] = 0.0f;
                    }
                    spq[lane] = (p << 8) | q;
                    shist[j][lane] = make_float2(cc, sn);
                    unsigned mk = __ballot_sync(0xffffffffu, rot);
                    if (lane == 0) { smask[j] = mk; if (mk) sAny = 1; }
                } else if (w == 1 && j == 0) {
                    // coset minima of {0,m1,m2,m3}: x < x^mi for all i
                    int cnt = 0;
                    #pragma unroll
                    for (int h = 0; h < 2; h++) {
                        int x = lane + 32 * h;
                        bool rep = (x < (x ^ m1)) && (x < (x ^ m2)) && (x < (x ^ m3));
                        unsigned bb = __ballot_sync(0xffffffffu, rep);
                        if (rep)
                            sreps[cnt + __popc(bb & ((1u << lane) - 1u))] = x;
                        cnt += __popc(bb);
                    }
                }
                __syncthreads();

                const unsigned mk = smask[j];
                if (mk) {
                    // --- A off-diagonal blocks (symmetric half) ---
                    #pragma unroll
                    for (int t = 0; t < 2; t++) {
                        int blk = tid + t * 256;
                        if (blk < 496) {
                            int bb = sblk[blk];
                            int bi = bb >> 8, bj = bb & 255;
                            if (((mk >> bi) | (mk >> bj)) & 1u) {
                                int pqi = spq[bi], pqj = spq[bj];
                                int pi = pqi >> 8, qi = pqi & 255;
                                int pj = pqj >> 8, qj = pqj & 255;
                                float2 gi = shist[j][bi], gj = shist[j][bj];
                                float a  = (pi < pj) ? sA[pi][pj] : sA[pj][pi];
                                float bv = (pi < qj) ? sA[pi][qj] : sA[qj][pi];
                                float c2 = (qi < pj) ? sA[qi][pj] : sA[pj][qi];
                                float d  = (qi < qj) ? sA[qi][qj] : sA[qj][qi];
                                float a1 = gj.x * a  - gj.y * bv;
                                float b1 = gj.y * a  + gj.x * bv;
                                float c1 = gj.x * c2 - gj.y * d;
                                float d1 = gj.y * c2 + gj.x * d;
                                float na = gi.x * a1 - gi.y * c1;
                                float nc = gi.y * a1 + gi.x * c1;
                                float nb = gi.x * b1 - gi.y * d1;
                                float nd = gi.y * b1 + gi.x * d1;
                                if (pi < pj) sA[pi][pj] = na; else sA[pj][pi] = na;
                                if (qi < pj) sA[qi][pj] = nc; else sA[pj][qi] = nc;
                                if (pi < qj) sA[pi][qj] = nb; else sA[qj][pi] = nb;
                                if (qi < qj) sA[qi][qj] = nd; else sA[qj][qi] = nd;
                            }
                        }
                    }
                }
                __syncthreads();
            }

            // --- V-pass for the whole group (3 rounds fused) ---
            const unsigned k1 = smask[0], k2 = smask[1], k3 = smask[2];
            if (k1 | k2 | k3) {
                const int b1 = 31 - __clz(m1);
                const int b2 = 31 - __clz(m2);
                const int b3 = 31 - __clz(m3);
                #pragma unroll
                for (int it = 0; it < 4; it++) {
                    int item = w * 4 + it;           // 0..31
                    int ci = item >> 1;
                    int row = ((item & 1) << 5) + lane;
                    int g0 = sreps[ci];
                    int ga = g0 ^ m1, gb = g0 ^ m2, gc = g0 ^ m3;
                    // slots & orientation flips (all warp-uniform)
                    int s01 = slot_of(g0, b1);
                    int f23 = (gb >> b1) & 1;
                    int s23 = slot_of(f23 ? gc : gb, b1);
                    int s02 = slot_of(g0, b2);
                    int f13 = (ga >> b2) & 1;
                    int s13 = slot_of(f13 ? gc : ga, b2);
                    int s03 = slot_of(g0, b3);
                    int f12 = (ga >> b3) & 1;
                    int s12 = slot_of(f12 ? gb : ga, b3);
                    int act = ((k1 >> s01) & 1) | ((k1 >> s23) & 1) |
                              ((k2 >> s02) & 1) | ((k2 >> s13) & 1) |
                              ((k3 >> s03) & 1) | ((k3 >> s12) & 1);
                    if (act) {
                        float v0 = sV[row][g0], v1 = sV[row][ga];
                        float v2 = sV[row][gb], v3 = sV[row][gc];
                        float2 cs;
                        cs = shist[0][s01]; rot2(v0, v1, cs.x, cs.y);
                        cs = shist[0][s23]; rot2(v2, v3, cs.x, f23 ? -cs.y : cs.y);
                        cs = shist[1][s02]; rot2(v0, v2, cs.x, cs.y);
                        cs = shist[1][s13]; rot2(v1, v3, cs.x, f13 ? -cs.y : cs.y);
                        cs = shist[2][s03]; rot2(v0, v3, cs.x, cs.y);
                        cs = shist[2][s12]; rot2(v1, v2, cs.x, f12 ? -cs.y : cs.y);
                        sV[row][g0] = v0; sV[row][ga] = v1;
                        sV[row][gb] = v2; sV[row][gc] = v3;
                    }
                }
            }
            __syncthreads();
        }
        int any = sAny;
        __syncthreads();
        if (!any) break;
    }

    // log of eigenvalues (natural order — no permutation with XOR schedule)
    if (tid < 64) sl[tid] = logf(fmaxf(sA[tid][tid], 1e-12f));
    __syncthreads();

    // logm = V * diag(log lambda) * V^T, 4x4 register tile per thread
    {
        int i0 = (tid >> 4) << 2;
        int j0 = (tid & 15) << 2;
        float acc[4][4];
        #pragma unroll
        for (int i = 0; i < 4; i++)
            #pragma unroll
            for (int j = 0; j < 4; j++) acc[i][j] = 0.0f;
        for (int k = 0; k < 64; k++) {
            float lk = sl[k];
            float ra0 = sV[i0 + 0][k], ra1 = sV[i0 + 1][k];
            float ra2 = sV[i0 + 2][k], ra3 = sV[i0 + 3][k];
            float rb0 = sV[j0 + 0][k] * lk, rb1 = sV[j0 + 1][k] * lk;
            float rb2 = sV[j0 + 2][k] * lk, rb3 = sV[j0 + 3][k] * lk;
            acc[0][0] += ra0 * rb0; acc[0][1] += ra0 * rb1;
            acc[0][2] += ra0 * rb2; acc[0][3] += ra0 * rb3;
            acc[1][0] += ra1 * rb0; acc[1][1] += ra1 * rb1;
            acc[1][2] += ra1 * rb2; acc[1][3] += ra1 * rb3;
            acc[2][0] += ra2 * rb0; acc[2][1] += ra2 * rb1;
            acc[2][2] += ra2 * rb2; acc[2][3] += ra2 * rb3;
            acc[3][0] += ra3 * rb0; acc[3][1] += ra3 * rb1;
            acc[3][2] += ra3 * rb2; acc[3][3] += ra3 * rb3;
        }
        float* out = dst + (size_t)blockIdx.x * MATSZ;
        #pragma unroll
        for (int i = 0; i < 4; i++) {
            float4 v = make_float4(acc[i][0], acc[i][1], acc[i][2], acc[i][3]);
            *(float4*)(out + (i0 + i) * 64 + j0) = v;
        }
    }
}

// ---------------------------------------------------------------------------
// q[c] = tr(logP_c * A_sym_c) = sum_k logP[c][k] * B[k][c]
// ---------------------------------------------------------------------------
__global__ void compute_q_kernel() {
    int c = blockIdx.x;
    int tid = threadIdx.x;
    __shared__ float sred[256];
    float acc = 0.0f;
    for (int k = tid; k < MATSZ; k += 256)
        acc += g_logP[(size_t)c * MATSZ + k] * g_B[(size_t)k * CDIM + c];
    sred[tid] = acc;
    __syncthreads();
    for (int o = 128; o > 0; o >>= 1) {
        if (tid < o) sred[tid] += sred[tid + o];
        __syncthreads();
    }
    if (tid == 0) g_q[c] = sred[0];
}

// ---------------------------------------------------------------------------
// SGEMM: out[M x 128] = logX[M x 4096] @ B[4096 x 128] - q[c]
// BM=64, BN=128, BK=16, TM=TN=8, 128 threads.
// ---------------------------------------------------------------------------
#define BM 64
#define BN 128
#define BK 16
__global__ __launch_bounds__(128) void gemm_kernel(
    const float* __restrict__ Amat, float* __restrict__ out) {
    __shared__ float As[BK][BM];   // transposed A tile
    __shared__ float Bs[BK][BN];
    __shared__ float sqv[BN];

    int tid = threadIdx.x;
    int rowg = tid >> 4;    // 0..7
    int colg = tid & 15;    // 0..15
    size_t row0 = (size_t)blockIdx.x * BM;

    if (tid < BN) sqv[tid] = g_q[tid];

    float acc[8][8];
    #pragma unroll
    for (int i = 0; i < 8; i++)
        #pragma unroll
        for (int j = 0; j < 8; j++) acc[i][j] = 0.0f;

    for (int kt = 0; kt < MATSZ; kt += BK) {
        #pragma unroll
        for (int l = 0; l < 2; l++) {
            int lin = tid + l * 128;
            int r = lin >> 2;
            int k4 = (lin & 3) * 4;
            float4 v = *(const float4*)(Amat + (row0 + r) * MATSZ + kt + k4);
            As[k4 + 0][r] = v.x; As[k4 + 1][r] = v.y;
            As[k4 + 2][r] = v.z; As[k4 + 3][r] = v.w;
        }
        #pragma unroll
        for (int l = 0; l < 4; l++) {
            int lin = tid + l * 128;
            int r = lin >> 5;
            int c4 = (lin & 31) * 4;
            *(float4*)&Bs[r][c4] =
                *(const float4*)(g_B + (size_t)(kt + r) * CDIM + c4);
        }
        __syncthreads();
        #pragma unroll
        for (int k = 0; k < BK; k++) {
            float ra[8], rb[8];
            #pragma unroll
            for (int i = 0; i < 8; i++) ra[i] = As[k][rowg * 8 + i];
            #pragma unroll
            for (int j = 0; j < 8; j++) rb[j] = Bs[k][colg * 8 + j];
            #pragma unroll
            for (int i = 0; i < 8; i++)
                #pragma unroll
                for (int j = 0; j < 8; j++)
                    acc[i][j] += ra[i] * rb[j];
        }
        __syncthreads();
    }
    #pragma unroll
    for (int i = 0; i < 8; i++) {
        size_t rr = row0 + rowg * 8 + i;
        #pragma unroll
        for (int j = 0; j < 8; j++) {
            int cc = colg * 8 + j;
            out[rr * CDIM + cc] = acc[i][j] - sqv[cc];
        }
    }
}

// ---------------------------------------------------------------------------
extern "C" void kernel_launch(void* const* d_in, const int* in_sizes, int n_in,
                              void* d_out, int out_size) {
    const float* X = (const float*)d_in[0];   // (32768, 64, 64)
    const float* P = (const float*)d_in[1];   // (128, 64, 64)
    const float* A = (const float*)d_in[2];   // (128, 64, 64)
    float* out = (float*)d_out;               // (32768, 128)

    float *p_logX, *p_logP;
    cudaGetSymbolAddress((void**)&p_logX, g_logX);
    cudaGetSymbolAddress((void**)&p_logP, g_logP);

    prep_b_kernel<<<(MATSZ * CDIM) / 256, 256>>>(A);
    jacobi_logm_kernel<<<CDIM, 256>>>(P, p_logP);
    compute_q_kernel<<<CDIM, 256>>>();
    jacobi_logm_kernel<<<NMAT, 256>>>(X, p_logX);
    gemm_kernel<<<NMAT / BM, 128>>>(p_logX, out);
}

// round 13
// speedup vs baseline: 2.2125x; 1.4185x over previous
#include <cuda_runtime.h>
#include <cstddef>

#define NMAT 32768
#define CDIM 128
#define NDIM 64
#define MATSZ 4096  // 64*64

// Scratch (static device arrays: the sanctioned alloc-free workaround)
__device__ float g_logX[(size_t)NMAT * MATSZ];   // 512 MB
__device__ float g_logP[CDIM * MATSZ];           // 2 MB
__device__ float g_B[MATSZ * CDIM];              // A_sym, k-major for GEMM (2 MB)
__device__ float g_q[CDIM];                      // tr(logP_c * A_sym_c)

// ---------------------------------------------------------------------------
// Build B[k][c] = A_sym_c[i][j], k = i*64+j, where A_sym = tril(A,-1)+tril^T+diag
// ---------------------------------------------------------------------------
__global__ void prep_b_kernel(const float* __restrict__ A) {
    int lin = blockIdx.x * blockDim.x + threadIdx.x;   // 0 .. 4096*128-1
    int c = lin & (CDIM - 1);
    int k = lin >> 7;
    int i = k >> 6, j = k & 63;
    float v;
    if (i == j)      v = A[(size_t)c * MATSZ + i * 64 + i];
    else if (i > j)  v = A[(size_t)c * MATSZ + i * 64 + j];
    else             v = A[(size_t)c * MATSZ + j * 64 + i];
    g_B[(size_t)k * CDIM + c] = v;
}

// ---------------------------------------------------------------------------
// One-sided Jacobi (Demmel-Veselic) logm. One CTA (256 threads) per matrix.
// 1) Cholesky X = L L^T in smem (column-major sG[col][row]).
// 2) Orthogonalize columns of L by Givens rotations: pair (p,q) handled by an
//    8-thread group; columns live in registers during the round, dots via
//    register FMA + 9 shuffles. Rotation applied (and stored) only if
//    dpq^2 > eps2*dpp*dqq (relative criterion == two-sided on L^T L).
// 3) lambda_i = ||g_i||^2, logm = sum_i (log l_i / l_i) g_i g_i^T.
// Converged when a full sweep applies no rotation.
// ---------------------------------------------------------------------------
__global__ __launch_bounds__(256, 4) void osj_logm_kernel(
    const float* __restrict__ src, float* __restrict__ dst) {
    __shared__ float sG[64][65];   // column-major: sG[col][row]
    __shared__ float sw[64];       // log(lam)/lam per column
    __shared__ float sinv;
    __shared__ int sAny;

    const int tid  = threadIdx.x;
    const int pair = tid >> 3;     // 0..31
    const int sub  = tid & 7;      // 0..7
    const float* Xm = src + (size_t)blockIdx.x * MATSZ;

    // Load (X symmetric: column-major == row-major)
    #pragma unroll
    for (int t = 0; t < 16; t++) {
        int idx = tid + t * 256;
        sG[idx >> 6][idx & 63] = Xm[idx];
    }
    __syncthreads();

    // In-place Cholesky (lower triangle, column-major access sG[c][r] = A[r][c])
    for (int j = 0; j < 64; j++) {
        if (tid == 0) sinv = rsqrtf(sG[j][j]);
        __syncthreads();
        if (tid < 64 - j) sG[j][j + tid] *= sinv;   // col j scaled; diag -> sqrt
        __syncthreads();
        for (int c = j + 1 + (tid >> 3); c < 64; c += 32) {
            float ljc = sG[j][c];
            #pragma unroll 4
            for (int r = c + (tid & 7); r < 64; r += 8)
                sG[c][r] -= sG[j][r] * ljc;
        }
        __syncthreads();
    }
    // Zero strict upper part of columns (r < c)
    #pragma unroll
    for (int t = 0; t < 16; t++) {
        int idx = tid + t * 256;
        int c = idx >> 6, r = idx & 63;
        if (r < c) sG[c][r] = 0.0f;
    }
    __syncthreads();

    const float eps2 = 4e-14f;   // (2e-7)^2 relative rotation threshold

    for (int sweep = 0; sweep < 14; sweep++) {
        if (tid == 0) sAny = 0;
        __syncthreads();
        for (int r = 0; r < 63; r++) {
            // circle-method pairing (orientation irrelevant for one-sided)
            int p, q;
            if (pair == 0) { p = 0; q = 1 + (r % 63); }
            else {
                p = 1 + ((pair + r) % 63);
                q = 1 + ((63 - pair + r) % 63);
            }
            // Load both columns, lane-interleaved (thread sub owns rows sub+8k)
            float gp[8], gq[8];
            #pragma unroll
            for (int k = 0; k < 8; k++) {
                gp[k] = sG[p][sub + 8 * k];
                gq[k] = sG[q][sub + 8 * k];
            }
            float dpp = 0.0f, dqq = 0.0f, dpq = 0.0f;
            #pragma unroll
            for (int k = 0; k < 8; k++) {
                dpp += gp[k] * gp[k];
                dqq += gq[k] * gq[k];
                dpq += gp[k] * gq[k];
            }
            #pragma unroll
            for (int o = 4; o > 0; o >>= 1) {
                dpp += __shfl_xor_sync(0xffffffffu, dpp, o);
                dqq += __shfl_xor_sync(0xffffffffu, dqq, o);
                dpq += __shfl_xor_sync(0xffffffffu, dpq, o);
            }
            if (dpq * dpq > eps2 * dpp * dqq) {
                float tau = (dqq - dpp) / (2.0f * dpq);
                float t = copysignf(1.0f, tau) /
                          (fabsf(tau) + sqrtf(1.0f + tau * tau));
                float cc = rsqrtf(1.0f + t * t);
                float sn = t * cc;
                #pragma unroll
                for (int k = 0; k < 8; k++) {
                    float x = gp[k], y = gq[k];
                    sG[p][sub + 8 * k] = cc * x - sn * y;
                    sG[q][sub + 8 * k] = sn * x + cc * y;
                }
                if (sub == 0) sAny = 1;   // benign race: all write 1
            }
            __syncthreads();
        }
        int any = sAny;
        __syncthreads();
        if (!any) break;
    }

    // Column norms -> weights w = log(lam)/lam
    {
        int col = tid >> 2, s4 = tid & 3;
        float acc = 0.0f;
        #pragma unroll
        for (int k = 0; k < 16; k++) {
            float v = sG[col][s4 * 16 + k];
            acc += v * v;
        }
        acc += __shfl_xor_sync(0xffffffffu, acc, 1);
        acc += __shfl_xor_sync(0xffffffffu, acc, 2);
        if (s4 == 0) {
            float lam = fmaxf(acc, 1e-12f);
            sw[col] = logf(lam) / lam;
        }
    }
    __syncthreads();

    // logm[i][j] = sum_k w_k * sG[k][i] * sG[k][j], 4x4 tile per thread
    {
        int i0 = (tid >> 4) << 2;
        int j0 = (tid & 15) << 2;
        float acc[4][4];
        #pragma unroll
        for (int i = 0; i < 4; i++)
            #pragma unroll
            for (int j = 0; j < 4; j++) acc[i][j] = 0.0f;
        for (int k = 0; k < 64; k++) {
            float wk = sw[k];
            float ra0 = sG[k][i0 + 0], ra1 = sG[k][i0 + 1];
            float ra2 = sG[k][i0 + 2], ra3 = sG[k][i0 + 3];
            float rb0 = sG[k][j0 + 0] * wk, rb1 = sG[k][j0 + 1] * wk;
            float rb2 = sG[k][j0 + 2] * wk, rb3 = sG[k][j0 + 3] * wk;
            acc[0][0] += ra0 * rb0; acc[0][1] += ra0 * rb1;
            acc[0][2] += ra0 * rb2; acc[0][3] += ra0 * rb3;
            acc[1][0] += ra1 * rb0; acc[1][1] += ra1 * rb1;
            acc[1][2] += ra1 * rb2; acc[1][3] += ra1 * rb3;
            acc[2][0] += ra2 * rb0; acc[2][1] += ra2 * rb1;
            acc[2][2] += ra2 * rb2; acc[2][3] += ra2 * rb3;
            acc[3][0] += ra3 * rb0; acc[3][1] += ra3 * rb1;
            acc[3][2] += ra3 * rb2; acc[3][3] += ra3 * rb3;
        }
        float* out = dst + (size_t)blockIdx.x * MATSZ;
        #pragma unroll
        for (int i = 0; i < 4; i++) {
            float4 v = make_float4(acc[i][0], acc[i][1], acc[i][2], acc[i][3]);
            *(float4*)(out + (i0 + i) * 64 + j0) = v;
        }
    }
}

// ---------------------------------------------------------------------------
// q[c] = tr(logP_c * A_sym_c) = sum_k logP[c][k] * B[k][c]
// ---------------------------------------------------------------------------
__global__ void compute_q_kernel() {
    int c = blockIdx.x;
    int tid = threadIdx.x;
    __shared__ float sred[256];
    float acc = 0.0f;
    for (int k = tid; k < MATSZ; k += 256)
        acc += g_logP[(size_t)c * MATSZ + k] * g_B[(size_t)k * CDIM + c];
    sred[tid] = acc;
    __syncthreads();
    for (int o = 128; o > 0; o >>= 1) {
        if (tid < o) sred[tid] += sred[tid + o];
        __syncthreads();
    }
    if (tid == 0) g_q[c] = sred[0];
}

// ---------------------------------------------------------------------------
// SGEMM: out[M x 128] = logX[M x 4096] @ B[4096 x 128] - q[c]
// BM=64, BN=128, BK=16, TM=TN=8, 128 threads.
// ---------------------------------------------------------------------------
#define BM 64
#define BN 128
#define BK 16
__global__ __launch_bounds__(128) void gemm_kernel(
    const float* __restrict__ Amat, float* __restrict__ out) {
    __shared__ float As[BK][BM];   // transposed A tile
    __shared__ float Bs[BK][BN];
    __shared__ float sqv[BN];

    int tid = threadIdx.x;
    int rowg = tid >> 4;    // 0..7
    int colg = tid & 15;    // 0..15
    size_t row0 = (size_t)blockIdx.x * BM;

    if (tid < BN) sqv[tid] = g_q[tid];

    float acc[8][8];
    #pragma unroll
    for (int i = 0; i < 8; i++)
        #pragma unroll
        for (int j = 0; j < 8; j++) acc[i][j] = 0.0f;

    for (int kt = 0; kt < MATSZ; kt += BK) {
        #pragma unroll
        for (int l = 0; l < 2; l++) {
            int lin = tid + l * 128;
            int r = lin >> 2;
            int k4 = (lin & 3) * 4;
            float4 v = *(const float4*)(Amat + (row0 + r) * MATSZ + kt + k4);
            As[k4 + 0][r] = v.x; As[k4 + 1][r] = v.y;
            As[k4 + 2][r] = v.z; As[k4 + 3][r] = v.w;
        }
        #pragma unroll
        for (int l = 0; l < 4; l++) {
            int lin = tid + l * 128;
            int r = lin >> 5;
            int c4 = (lin & 31) * 4;
            *(float4*)&Bs[r][c4] =
                *(const float4*)(g_B + (size_t)(kt + r) * CDIM + c4);
        }
        __syncthreads();
        #pragma unroll
        for (int k = 0; k < BK; k++) {
            float ra[8], rb[8];
            #pragma unroll
            for (int i = 0; i < 8; i++) ra[i] = As[k][rowg * 8 + i];
            #pragma unroll
            for (int j = 0; j < 8; j++) rb[j] = Bs[k][colg * 8 + j];
            #pragma unroll
            for (int i = 0; i < 8; i++)
                #pragma unroll
                for (int j = 0; j < 8; j++)
                    acc[i][j] += ra[i] * rb[j];
        }
        __syncthreads();
    }
    #pragma unroll
    for (int i = 0; i < 8; i++) {
        size_t rr = row0 + rowg * 8 + i;
        #pragma unroll
        for (int j = 0; j < 8; j++) {
            int cc = colg * 8 + j;
            out[rr * CDIM + cc] = acc[i][j] - sqv[cc];
        }
    }
}

// ---------------------------------------------------------------------------
extern "C" void kernel_launch(void* const* d_in, const int* in_sizes, int n_in,
                              void* d_out, int out_size) {
    const float* X = (const float*)d_in[0];   // (32768, 64, 64)
    const float* P = (const float*)d_in[1];   // (128, 64, 64)
    const float* A = (const float*)d_in[2];   // (128, 64, 64)
    float* out = (float*)d_out;               // (32768, 128)

    float *p_logX, *p_logP;
    cudaGetSymbolAddress((void**)&p_logX, g_logX);
    cudaGetSymbolAddress((void**)&p_logP, g_logP);

    prep_b_kernel<<<(MATSZ * CDIM) / 256, 256>>>(A);
    osj_logm_kernel<<<CDIM, 256>>>(P, p_logP);
    compute_q_kernel<<<CDIM, 256>>>();
    osj_logm_kernel<<<NMAT, 256>>>(X, p_logX);
    gemm_kernel<<<NMAT / BM, 128>>>(p_logX, out);
}

// round 14
// speedup vs baseline: 3.4428x; 1.5561x over previous
#include <cuda_runtime.h>
#include <cstddef>

#define NMAT 32768
#define CDIM 128
#define NDIM 64
#define MATSZ 4096  // 64*64
#define GSTR 68     // column stride (floats): 16B-aligned rows, 272B stride

// Scratch (static device arrays: the sanctioned alloc-free workaround)
__device__ float g_logX[(size_t)NMAT * MATSZ];   // 512 MB
__device__ float g_logP[CDIM * MATSZ];           // 2 MB
__device__ float g_B[MATSZ * CDIM];              // A_sym, k-major for GEMM (2 MB)
__device__ float g_q[CDIM];                      // tr(logP_c * A_sym_c)

// ---------------------------------------------------------------------------
// Build B[k][c] = A_sym_c[i][j], k = i*64+j, where A_sym = tril(A,-1)+tril^T+diag
// ---------------------------------------------------------------------------
__global__ void prep_b_kernel(const float* __restrict__ A) {
    int lin = blockIdx.x * blockDim.x + threadIdx.x;   // 0 .. 4096*128-1
    int c = lin & (CDIM - 1);
    int k = lin >> 7;
    int i = k >> 6, j = k & 63;
    float v;
    if (i == j)      v = A[(size_t)c * MATSZ + i * 64 + i];
    else if (i > j)  v = A[(size_t)c * MATSZ + i * 64 + j];
    else             v = A[(size_t)c * MATSZ + j * 64 + i];
    g_B[(size_t)k * CDIM + c] = v;
}

// ---------------------------------------------------------------------------
// One-sided Jacobi logm with XOR-quadruple scheduling.
// One CTA (256 threads) per 64x64 SPD matrix.
// 1) LDLT factor X = W D^-1 W^T (W = L*D in lower triangle), then scale
//    columns by rsqrt(d): G columns with X = G G^T; initial norms tracked.
// 2) 63 rotation rounds/sweep as 21 groups of 3: masks {m1,m2,m1^m2}
//    (GF(4)* cosets of GF(64)*). The 4-column cosets of {0,m1,m2,m3} are
//    closed under all 3 pairings with FIXED positional pairs, so a 16-thread
//    group loads 4 columns into registers once, applies all 6 rotations
//    (dots: 4 FMA + 4-step butterfly; dpp/dqq from incrementally tracked
//    norms), stores once (skipped if nothing rotated).
// 3) lambda_i = ||g_i||^2 (recomputed exactly), logm = sum w_i g_i g_i^T.
// ---------------------------------------------------------------------------
__global__ __launch_bounds__(256, 4) void osj_logm_kernel(
    const float* __restrict__ src, float* __restrict__ dst) {
    __shared__ float sG[64][GSTR];      // column-major: sG[col][row]
    __shared__ float snorm[64];         // tracked squared column norms
    __shared__ float sw[64];            // log(lam)/lam weights
    __shared__ unsigned char spow[64];  // GF(64)* powers of x
    __shared__ unsigned char sreps[21][16]; // coset reps per group
    __shared__ int sAny;

    const int tid  = threadIdx.x;
    const int lane = tid & 31;
    const int w    = tid >> 5;
    const float* Xm = src + (size_t)blockIdx.x * MATSZ;

    // GF(64) power table: x^6 = x + 1 (primitive poly 0x43)
    if (tid == 0) {
        unsigned v = 1;
        for (int i = 0; i < 63; i++) {
            spow[i] = (unsigned char)v;
            v <<= 1;
            if (v & 64) v ^= 0x43;
        }
    }
    // Load X, zeroing the strict upper part of each column (r < c)
    #pragma unroll
    for (int t = 0; t < 16; t++) {
        int idx = tid + t * 256;
        int c = idx >> 6, r = idx & 63;
        sG[c][r] = (r < c) ? 0.0f : Xm[idx];
    }
    __syncthreads();

    // Coset-representative table (uses spow; consumed only after many barriers)
    for (int grp = w; grp < 21; grp += 8) {
        int m1 = spow[grp], m2 = spow[grp + 21], m3 = m1 ^ m2;
        int cnt = 0;
        #pragma unroll
        for (int h = 0; h < 2; h++) {
            int x = lane + 32 * h;
            bool rep = (x < (x ^ m1)) && (x < (x ^ m2)) && (x < (x ^ m3));
            unsigned bb = __ballot_sync(0xffffffffu, rep);
            if (rep)
                sreps[grp][cnt + __popc(bb & ((1u << lane) - 1u))] =
                    (unsigned char)x;
            cnt += __popc(bb);
        }
    }

    // LDLT (right-looking, unscaled W = L*D in lower triangle), 1 barrier/step
    for (int j = 0; j < 64; j++) {
        float recip = __frcp_rn(sG[j][j]);
        for (int c = j + 1 + (tid >> 3); c < 64; c += 32) {
            float wjc = sG[j][c] * recip;
            #pragma unroll 4
            for (int r = c + (tid & 7); r < 64; r += 8)
                sG[c][r] -= sG[j][r] * wjc;
        }
        __syncthreads();
    }
    // Scale columns: G[:,j] = W[:,j] * rsqrt(d_j); fused initial norms.
    {
        int col = tid >> 2, s4 = tid & 3;
        float s = rsqrtf(sG[col][col]);
        __syncwarp();
        float acc = 0.0f;
        #pragma unroll
        for (int k = 0; k < 16; k++) {
            int r = s4 + 4 * k;
            float v = sG[col][r] * s;
            sG[col][r] = v;
            acc += v * v;
        }
        acc += __shfl_xor_sync(0xffffffffu, acc, 1);
        acc += __shfl_xor_sync(0xffffffffu, acc, 2);
        if (s4 == 0) snorm[col] = acc;
    }
    __syncthreads();

    const float eps2 = 4e-14f;   // (2e-7)^2 relative rotation threshold
    const int ci  = tid >> 4;    // coset index 0..15
    const int sub = tid & 15;    // sub-thread: owns rows 4*sub..4*sub+3

    for (int sweep = 0; sweep < 14; sweep++) {
        if (tid == 0) sAny = 0;
        __syncthreads();
        for (int grp = 0; grp < 21; grp++) {
            const int m1 = spow[grp], m2 = spow[grp + 21], m3 = m1 ^ m2;
            const int c0 = sreps[grp][ci];
            const int c1 = c0 ^ m1, c2 = c0 ^ m2, c3 = c0 ^ m3;
            // Load 4 columns (4 rows each) + norms
            float g[4][4];
            *(float4*)g[0] = *(const float4*)&sG[c0][4 * sub];
            *(float4*)g[1] = *(const float4*)&sG[c1][4 * sub];
            *(float4*)g[2] = *(const float4*)&sG[c2][4 * sub];
            *(float4*)g[3] = *(const float4*)&sG[c3][4 * sub];
            float n[4] = { snorm[c0], snorm[c1], snorm[c2], snorm[c3] };
            bool any = false;

            // 6 rotations: rounds m1:(01)(23)  m2:(02)(13)  m3:(03)(12)
            #pragma unroll
            for (int rr = 0; rr < 3; rr++) {
                #pragma unroll
                for (int h = 0; h < 2; h++) {
                    int x, y;
                    if (rr == 0) { x = h ? 2 : 0; y = h ? 3 : 1; }
                    else if (rr == 1) { x = h ? 1 : 0; y = h ? 3 : 2; }
                    else { x = h ? 1 : 0; y = h ? 2 : 3; }
                    float dpq = g[x][0] * g[y][0] + g[x][1] * g[y][1]
                              + g[x][2] * g[y][2] + g[x][3] * g[y][3];
                    dpq += __shfl_xor_sync(0xffffffffu, dpq, 1);
                    dpq += __shfl_xor_sync(0xffffffffu, dpq, 2);
                    dpq += __shfl_xor_sync(0xffffffffu, dpq, 4);
                    dpq += __shfl_xor_sync(0xffffffffu, dpq, 8);
                    if (dpq * dpq > eps2 * n[x] * n[y]) {
                        float tau = (n[y] - n[x]) / (2.0f * dpq);
                        float t = copysignf(1.0f, tau) /
                                  (fabsf(tau) + sqrtf(1.0f + tau * tau));
                        float cc = rsqrtf(1.0f + t * t);
                        float sn = t * cc;
                        #pragma unroll
                        for (int k = 0; k < 4; k++) {
                            float a = g[x][k], b = g[y][k];
                            g[x][k] = cc * a - sn * b;
                            g[y][k] = sn * a + cc * b;
                        }
                        n[x] -= t * dpq;
                        n[y] += t * dpq;
                        any = true;
                    }
                }
            }
            if (any) {
                *(float4*)&sG[c0][4 * sub] = *(float4*)g[0];
                *(float4*)&sG[c1][4 * sub] = *(float4*)g[1];
                *(float4*)&sG[c2][4 * sub] = *(float4*)g[2];
                *(float4*)&sG[c3][4 * sub] = *(float4*)g[3];
                if (sub == 0) {
                    snorm[c0] = n[0]; snorm[c1] = n[1];
                    snorm[c2] = n[2]; snorm[c3] = n[3];
                    sAny = 1;
                }
            }
            __syncthreads();
        }
        int anyAll = sAny;
        __syncthreads();
        if (!anyAll) break;
    }

    // Exact column norms -> weights w = log(lam)/lam
    {
        int col = tid >> 2, s4 = tid & 3;
        float acc = 0.0f;
        #pragma unroll
        for (int k = 0; k < 16; k++) {
            float v = sG[col][s4 * 16 + k];
            acc += v * v;
        }
        acc += __shfl_xor_sync(0xffffffffu, acc, 1);
        acc += __shfl_xor_sync(0xffffffffu, acc, 2);
        if (s4 == 0) {
            float lam = fmaxf(acc, 1e-12f);
            sw[col] = logf(lam) / lam;
        }
    }
    __syncthreads();

    // logm[i][j] = sum_k w_k * sG[k][i] * sG[k][j], 4x4 tile per thread
    {
        int i0 = (tid >> 4) << 2;
        int j0 = (tid & 15) << 2;
        float acc[4][4];
        #pragma unroll
        for (int i = 0; i < 4; i++)
            #pragma unroll
            for (int j = 0; j < 4; j++) acc[i][j] = 0.0f;
        for (int k = 0; k < 64; k++) {
            float wk = sw[k];
            float ra0 = sG[k][i0 + 0], ra1 = sG[k][i0 + 1];
            float ra2 = sG[k][i0 + 2], ra3 = sG[k][i0 + 3];
            float rb0 = sG[k][j0 + 0] * wk, rb1 = sG[k][j0 + 1] * wk;
            float rb2 = sG[k][j0 + 2] * wk, rb3 = sG[k][j0 + 3] * wk;
            acc[0][0] += ra0 * rb0; acc[0][1] += ra0 * rb1;
            acc[0][2] += ra0 * rb2; acc[0][3] += ra0 * rb3;
            acc[1][0] += ra1 * rb0; acc[1][1] += ra1 * rb1;
            acc[1][2] += ra1 * rb2; acc[1][3] += ra1 * rb3;
            acc[2][0] += ra2 * rb0; acc[2][1] += ra2 * rb1;
            acc[2][2] += ra2 * rb2; acc[2][3] += ra2 * rb3;
            acc[3][0] += ra3 * rb0; acc[3][1] += ra3 * rb1;
            acc[3][2] += ra3 * rb2; acc[3][3] += ra3 * rb3;
        }
        float* out = dst + (size_t)blockIdx.x * MATSZ;
        #pragma unroll
        for (int i = 0; i < 4; i++) {
            float4 v = make_float4(acc[i][0], acc[i][1], acc[i][2], acc[i][3]);
            *(float4*)(out + (i0 + i) * 64 + j0) = v;
        }
    }
}

// ---------------------------------------------------------------------------
// q[c] = tr(logP_c * A_sym_c) = sum_k logP[c][k] * B[k][c]
// ---------------------------------------------------------------------------
__global__ void compute_q_kernel() {
    int c = blockIdx.x;
    int tid = threadIdx.x;
    __shared__ float sred[256];
    float acc = 0.0f;
    for (int k = tid; k < MATSZ; k += 256)
        acc += g_logP[(size_t)c * MATSZ + k] * g_B[(size_t)k * CDIM + c];
    sred[tid] = acc;
    __syncthreads();
    for (int o = 128; o > 0; o >>= 1) {
        if (tid < o) sred[tid] += sred[tid + o];
        __syncthreads();
    }
    if (tid == 0) g_q[c] = sred[0];
}

// ---------------------------------------------------------------------------
// SGEMM: out[M x 128] = logX[M x 4096] @ B[4096 x 128] - q[c]
// BM=64, BN=128, BK=16, TM=TN=8, 128 threads.
// ---------------------------------------------------------------------------
#define BM 64
#define BN 128
#define BK 16
__global__ __launch_bounds__(128) void gemm_kernel(
    const float* __restrict__ Amat, float* __restrict__ out) {
    __shared__ float As[BK][BM];   // transposed A tile
    __shared__ float Bs[BK][BN];
    __shared__ float sqv[BN];

    int tid = threadIdx.x;
    int rowg = tid >> 4;    // 0..7
    int colg = tid & 15;    // 0..15
    size_t row0 = (size_t)blockIdx.x * BM;

    if (tid < BN) sqv[tid] = g_q[tid];

    float acc[8][8];
    #pragma unroll
    for (int i = 0; i < 8; i++)
        #pragma unroll
        for (int j = 0; j < 8; j++) acc[i][j] = 0.0f;

    for (int kt = 0; kt < MATSZ; kt += BK) {
        #pragma unroll
        for (int l = 0; l < 2; l++) {
            int lin = tid + l * 128;
            int r = lin >> 2;
            int k4 = (lin & 3) * 4;
            float4 v = *(const float4*)(Amat + (row0 + r) * MATSZ + kt + k4);
            As[k4 + 0][r] = v.x; As[k4 + 1][r] = v.y;
            As[k4 + 2][r] = v.z; As[k4 + 3][r] = v.w;
        }
        #pragma unroll
        for (int l = 0; l < 4; l++) {
            int lin = tid + l * 128;
            int r = lin >> 5;
            int c4 = (lin & 31) * 4;
            *(float4*)&Bs[r][c4] =
                *(const float4*)(g_B + (size_t)(kt + r) * CDIM + c4);
        }
        __syncthreads();
        #pragma unroll
        for (int k = 0; k < BK; k++) {
            float ra[8], rb[8];
            #pragma unroll
            for (int i = 0; i < 8; i++) ra[i] = As[k][rowg * 8 + i];
            #pragma unroll
            for (int j = 0; j < 8; j++) rb[j] = Bs[k][colg * 8 + j];
            #pragma unroll
            for (int i = 0; i < 8; i++)
                #pragma unroll
                for (int j = 0; j < 8; j++)
                    acc[i][j] += ra[i] * rb[j];
        }
        __syncthreads();
    }
    #pragma unroll
    for (int i = 0; i < 8; i++) {
        size_t rr = row0 + rowg * 8 + i;
        #pragma unroll
        for (int j = 0; j < 8; j++) {
            int cc = colg * 8 + j;
            out[rr * CDIM + cc] = acc[i][j] - sqv[cc];
        }
    }
}

// ---------------------------------------------------------------------------
extern "C" void kernel_launch(void* const* d_in, const int* in_sizes, int n_in,
                              void* d_out, int out_size) {
    const float* X = (const float*)d_in[0];   // (32768, 64, 64)
    const float* P = (const float*)d_in[1];   // (128, 64, 64)
    const float* A = (const float*)d_in[2];   // (128, 64, 64)
    float* out = (float*)d_out;               // (32768, 128)

    float *p_logX, *p_logP;
    cudaGetSymbolAddress((void**)&p_logX, g_logX);
    cudaGetSymbolAddress((void**)&p_logP, g_logP);

    prep_b_kernel<<<(MATSZ * CDIM) / 256, 256>>>(A);
    osj_logm_kernel<<<CDIM, 256>>>(P, p_logP);
    compute_q_kernel<<<CDIM, 256>>>();
    osj_logm_kernel<<<NMAT, 256>>>(X, p_logX);
    gemm_kernel<<<NMAT / BM, 128>>>(p_logX, out);
}

// round 15
// speedup vs baseline: 5.9998x; 1.7427x over previous
#include <cuda_runtime.h>
#include <cstddef>

#define NMAT 32768
#define CDIM 128
#define NDIM 64
#define MATSZ 4096  // 64*64
#define GSTR 68     // column stride (floats): 16B-aligned rows, 272B stride

// Scratch (static device arrays: the sanctioned alloc-free workaround)
__device__ float g_logX[(size_t)NMAT * MATSZ];   // 512 MB
__device__ float g_logP[CDIM * MATSZ];           // 2 MB
__device__ float g_B[MATSZ * CDIM];              // A_sym, k-major for GEMM (2 MB)
__device__ float g_q[CDIM];                      // tr(logP_c * A_sym_c)

// ---------------------------------------------------------------------------
// Build B[k][c] = A_sym_c[i][j], k = i*64+j, where A_sym = tril(A,-1)+tril^T+diag
// ---------------------------------------------------------------------------
__global__ void prep_b_kernel(const float* __restrict__ A) {
    int lin = blockIdx.x * blockDim.x + threadIdx.x;   // 0 .. 4096*128-1
    int c = lin & (CDIM - 1);
    int k = lin >> 7;
    int i = k >> 6, j = k & 63;
    float v;
    if (i == j)      v = A[(size_t)c * MATSZ + i * 64 + i];
    else if (i > j)  v = A[(size_t)c * MATSZ + i * 64 + j];
    else             v = A[(size_t)c * MATSZ + j * 64 + i];
    g_B[(size_t)k * CDIM + c] = v;
}

// ---------------------------------------------------------------------------
// One-sided Jacobi logm with XOR-quadruple scheduling.
// One CTA (256 threads) per 64x64 SPD matrix.
// 1) LDLT factor X = W D^-1 W^T, scale columns by rsqrt(d): X = G G^T.
// 2) 63 rounds/sweep as 21 groups of 3 (masks {m1,m2,m1^m2}, GF(4)* cosets).
//    4-column cosets of {0,m1,m2,m3} are closed under all 3 pairings with
//    fixed positional pairs; 16-thread group keeps 4 columns in registers
//    across the 3 rounds. Rotations are BRANCHLESS (inactive pair -> exact
//    identity via t=0) with fast-intrinsic parameter math; norms tracked
//    incrementally; stores skipped when no pair in the group rotated.
// 3) lambda_i = ||g_i||^2 (recomputed exactly), logm = sum w_i g_i g_i^T.
// ---------------------------------------------------------------------------
__global__ __launch_bounds__(256, 4) void osj_logm_kernel(
    const float* __restrict__ src, float* __restrict__ dst) {
    __shared__ float sG[64][GSTR];      // column-major: sG[col][row]
    __shared__ float snorm[64];         // tracked squared column norms
    __shared__ float sw[64];            // log(lam)/lam weights
    __shared__ unsigned char spow[64];  // GF(64)* powers of x
    __shared__ unsigned char sreps[21][16]; // coset reps per group
    __shared__ int sAny;

    const int tid  = threadIdx.x;
    const int lane = tid & 31;
    const int w    = tid >> 5;
    const float* Xm = src + (size_t)blockIdx.x * MATSZ;

    // GF(64) power table: x^6 = x + 1 (primitive poly 0x43)
    if (tid == 0) {
        unsigned v = 1;
        for (int i = 0; i < 63; i++) {
            spow[i] = (unsigned char)v;
            v <<= 1;
            if (v & 64) v ^= 0x43;
        }
    }
    // Load X, zeroing the strict upper part of each column (r < c)
    #pragma unroll
    for (int t = 0; t < 16; t++) {
        int idx = tid + t * 256;
        int c = idx >> 6, r = idx & 63;
        sG[c][r] = (r < c) ? 0.0f : Xm[idx];
    }
    __syncthreads();

    // Coset-representative table (uses spow; consumed only after many barriers)
    for (int grp = w; grp < 21; grp += 8) {
        int m1 = spow[grp], m2 = spow[grp + 21], m3 = m1 ^ m2;
        int cnt = 0;
        #pragma unroll
        for (int h = 0; h < 2; h++) {
            int x = lane + 32 * h;
            bool rep = (x < (x ^ m1)) && (x < (x ^ m2)) && (x < (x ^ m3));
            unsigned bb = __ballot_sync(0xffffffffu, rep);
            if (rep)
                sreps[grp][cnt + __popc(bb & ((1u << lane) - 1u))] =
                    (unsigned char)x;
            cnt += __popc(bb);
        }
    }

    // LDLT (right-looking, unscaled W = L*D in lower triangle), 1 barrier/step
    for (int j = 0; j < 64; j++) {
        float recip = __frcp_rn(sG[j][j]);
        for (int c = j + 1 + (tid >> 3); c < 64; c += 32) {
            float wjc = sG[j][c] * recip;
            #pragma unroll 4
            for (int r = c + (tid & 7); r < 64; r += 8)
                sG[c][r] -= sG[j][r] * wjc;
        }
        __syncthreads();
    }
    // Scale columns: G[:,j] = W[:,j] * rsqrt(d_j); fused initial norms.
    {
        int col = tid >> 2, s4 = tid & 3;
        float s = rsqrtf(sG[col][col]);
        __syncwarp();
        float acc = 0.0f;
        #pragma unroll
        for (int k = 0; k < 16; k++) {
            int r = s4 + 4 * k;
            float v = sG[col][r] * s;
            sG[col][r] = v;
            acc += v * v;
        }
        acc += __shfl_xor_sync(0xffffffffu, acc, 1);
        acc += __shfl_xor_sync(0xffffffffu, acc, 2);
        if (s4 == 0) snorm[col] = acc;
    }
    __syncthreads();

    const float eps2 = 4e-14f;   // (2e-7)^2 relative rotation threshold
    const int ci  = tid >> 4;    // coset index 0..15
    const int sub = tid & 15;    // sub-thread: owns rows 4*sub..4*sub+3

    for (int sweep = 0; sweep < 14; sweep++) {
        if (tid == 0) sAny = 0;
        __syncthreads();
        for (int grp = 0; grp < 21; grp++) {
            const int m1 = spow[grp], m2 = spow[grp + 21], m3 = m1 ^ m2;
            const int c0 = sreps[grp][ci];
            const int c1 = c0 ^ m1, c2 = c0 ^ m2, c3 = c0 ^ m3;
            // Load 4 columns (4 rows each) + norms
            float g[4][4];
            *(float4*)g[0] = *(const float4*)&sG[c0][4 * sub];
            *(float4*)g[1] = *(const float4*)&sG[c1][4 * sub];
            *(float4*)g[2] = *(const float4*)&sG[c2][4 * sub];
            *(float4*)g[3] = *(const float4*)&sG[c3][4 * sub];
            float n[4] = { snorm[c0], snorm[c1], snorm[c2], snorm[c3] };
            bool anyv = false;

            // 6 rotations: rounds m1:(01)(23)  m2:(02)(13)  m3:(03)(12)
            // Branchless: inactive -> t=0 -> cc=1, sn=0 (exact identity).
            #pragma unroll
            for (int rr = 0; rr < 3; rr++) {
                #pragma unroll
                for (int h = 0; h < 2; h++) {
                    int x, y;
                    if (rr == 0) { x = h ? 2 : 0; y = h ? 3 : 1; }
                    else if (rr == 1) { x = h ? 1 : 0; y = h ? 3 : 2; }
                    else { x = h ? 1 : 0; y = h ? 2 : 3; }
                    float dpq = g[x][0] * g[y][0] + g[x][1] * g[y][1]
                              + g[x][2] * g[y][2] + g[x][3] * g[y][3];
                    dpq += __shfl_xor_sync(0xffffffffu, dpq, 1);
                    dpq += __shfl_xor_sync(0xffffffffu, dpq, 2);
                    dpq += __shfl_xor_sync(0xffffffffu, dpq, 4);
                    dpq += __shfl_xor_sync(0xffffffffu, dpq, 8);
                    bool active = (dpq * dpq > eps2 * n[x] * n[y]);
                    float dsafe = active ? dpq : 1.0f;
                    float tau = __fdividef(n[y] - n[x], 2.0f * dsafe);
                    float tt = fmaf(tau, tau, 1.0f);
                    float sq = tt * rsqrtf(tt);              // sqrt(1+tau^2)
                    float t = copysignf(__fdividef(1.0f, fabsf(tau) + sq), tau);
                    t = active ? t : 0.0f;
                    float cc = rsqrtf(fmaf(t, t, 1.0f));     // t=0 -> exactly 1
                    float sn = t * cc;
                    #pragma unroll
                    for (int k = 0; k < 4; k++) {
                        float a = g[x][k], b = g[y][k];
                        g[x][k] = cc * a - sn * b;
                        g[y][k] = sn * a + cc * b;
                    }
                    float tdpq = t * dpq;
                    n[x] -= tdpq;
                    n[y] += tdpq;
                    anyv |= active;
                }
            }
            if (anyv) {
                *(float4*)&sG[c0][4 * sub] = *(float4*)g[0];
                *(float4*)&sG[c1][4 * sub] = *(float4*)g[1];
                *(float4*)&sG[c2][4 * sub] = *(float4*)g[2];
                *(float4*)&sG[c3][4 * sub] = *(float4*)g[3];
                if (sub == 0) {
                    snorm[c0] = n[0]; snorm[c1] = n[1];
                    snorm[c2] = n[2]; snorm[c3] = n[3];
                    sAny = 1;
                }
            }
            __syncthreads();
        }
        int anyAll = sAny;
        __syncthreads();
        if (!anyAll) break;
    }

    // Exact column norms -> weights w = log(lam)/lam  (float4 loads)
    {
        int col = tid >> 2, s4 = tid & 3;
        float acc = 0.0f;
        #pragma unroll
        for (int k = 0; k < 4; k++) {
            float4 v = *(const float4*)&sG[col][s4 * 16 + 4 * k];
            acc += v.x * v.x + v.y * v.y + v.z * v.z + v.w * v.w;
        }
        acc += __shfl_xor_sync(0xffffffffu, acc, 1);
        acc += __shfl_xor_sync(0xffffffffu, acc, 2);
        if (s4 == 0) {
            float lam = fmaxf(acc, 1e-12f);
            sw[col] = logf(lam) / lam;
        }
    }
    __syncthreads();

    // logm[i][j] = sum_k w_k * sG[k][i] * sG[k][j], 4x4 tile, float4 loads
    {
        int i0 = (tid >> 4) << 2;
        int j0 = (tid & 15) << 2;
        float acc[4][4];
        #pragma unroll
        for (int i = 0; i < 4; i++)
            #pragma unroll
            for (int j = 0; j < 4; j++) acc[i][j] = 0.0f;
        for (int k = 0; k < 64; k++) {
            float wk = sw[k];
            float4 ra = *(const float4*)&sG[k][i0];
            float4 rb = *(const float4*)&sG[k][j0];
            float rb0 = rb.x * wk, rb1 = rb.y * wk;
            float rb2 = rb.z * wk, rb3 = rb.w * wk;
            acc[0][0] += ra.x * rb0; acc[0][1] += ra.x * rb1;
            acc[0][2] += ra.x * rb2; acc[0][3] += ra.x * rb3;
            acc[1][0] += ra.y * rb0; acc[1][1] += ra.y * rb1;
            acc[1][2] += ra.y * rb2; acc[1][3] += ra.y * rb3;
            acc[2][0] += ra.z * rb0; acc[2][1] += ra.z * rb1;
            acc[2][2] += ra.z * rb2; acc[2][3] += ra.z * rb3;
            acc[3][0] += ra.w * rb0; acc[3][1] += ra.w * rb1;
            acc[3][2] += ra.w * rb2; acc[3][3] += ra.w * rb3;
        }
        float* out = dst + (size_t)blockIdx.x * MATSZ;
        #pragma unroll
        for (int i = 0; i < 4; i++) {
            float4 v = make_float4(acc[i][0], acc[i][1], acc[i][2], acc[i][3]);
            *(float4*)(out + (i0 + i) * 64 + j0) = v;
        }
    }
}

// ---------------------------------------------------------------------------
// q[c] = tr(logP_c * A_sym_c) = sum_k logP[c][k] * B[k][c]
// ---------------------------------------------------------------------------
__global__ void compute_q_kernel() {
    int c = blockIdx.x;
    int tid = threadIdx.x;
    __shared__ float sred[256];
    float acc = 0.0f;
    for (int k = tid; k < MATSZ; k += 256)
        acc += g_logP[(size_t)c * MATSZ + k] * g_B[(size_t)k * CDIM + c];
    sred[tid] = acc;
    __syncthreads();
    for (int o = 128; o > 0; o >>= 1) {
        if (tid < o) sred[tid] += sred[tid + o];
        __syncthreads();
    }
    if (tid == 0) g_q[c] = sred[0];
}

// ---------------------------------------------------------------------------
// SGEMM: out[M x 128] = logX[M x 4096] @ B[4096 x 128] - q[c]
// BM=64, BN=128, BK=16, TM=TN=8, 128 threads.
// ---------------------------------------------------------------------------
#define BM 64
#define BN 128
#define BK 16
__global__ __launch_bounds__(128) void gemm_kernel(
    const float* __restrict__ Amat, float* __restrict__ out) {
    __shared__ float As[BK][BM];   // transposed A tile
    __shared__ float Bs[BK][BN];
    __shared__ float sqv[BN];

    int tid = threadIdx.x;
    int rowg = tid >> 4;    // 0..7
    int colg = tid & 15;    // 0..15
    size_t row0 = (size_t)blockIdx.x * BM;

    if (tid < BN) sqv[tid] = g_q[tid];

    float acc[8][8];
    #pragma unroll
    for (int i = 0; i < 8; i++)
        #pragma unroll
        for (int j = 0; j < 8; j++) acc[i][j] = 0.0f;

    for (int kt = 0; kt < MATSZ; kt += BK) {
        #pragma unroll
        for (int l = 0; l < 2; l++) {
            int lin = tid + l * 128;
            int r = lin >> 2;
            int k4 = (lin & 3) * 4;
            float4 v = *(const float4*)(Amat + (row0 + r) * MATSZ + kt + k4);
            As[k4 + 0][r] = v.x; As[k4 + 1][r] = v.y;
            As[k4 + 2][r] = v.z; As[k4 + 3][r] = v.w;
        }
        #pragma unroll
        for (int l = 0; l < 4; l++) {
            int lin = tid + l * 128;
            int r = lin >> 5;
            int c4 = (lin & 31) * 4;
            *(float4*)&Bs[r][c4] =
                *(const float4*)(g_B + (size_t)(kt + r) * CDIM + c4);
        }
        __syncthreads();
        #pragma unroll
        for (int k = 0; k < BK; k++) {
            float ra[8], rb[8];
            #pragma unroll
            for (int i = 0; i < 8; i++) ra[i] = As[k][rowg * 8 + i];
            #pragma unroll
            for (int j = 0; j < 8; j++) rb[j] = Bs[k][colg * 8 + j];
            #pragma unroll
            for (int i = 0; i < 8; i++)
                #pragma unroll
                for (int j = 0; j < 8; j++)
                    acc[i][j] += ra[i] * rb[j];
        }
        __syncthreads();
    }
    #pragma unroll
    for (int i = 0; i < 8; i++) {
        size_t rr = row0 + rowg * 8 + i;
        #pragma unroll
        for (int j = 0; j < 8; j++) {
            int cc = colg * 8 + j;
            out[rr * CDIM + cc] = acc[i][j] - sqv[cc];
        }
    }
}

// ---------------------------------------------------------------------------
extern "C" void kernel_launch(void* const* d_in, const int* in_sizes, int n_in,
                              void* d_out, int out_size) {
    const float* X = (const float*)d_in[0];   // (32768, 64, 64)
    const float* P = (const float*)d_in[1];   // (128, 64, 64)
    const float* A = (const float*)d_in[2];   // (128, 64, 64)
    float* out = (float*)d_out;               // (32768, 128)

    float *p_logX, *p_logP;
    cudaGetSymbolAddress((void**)&p_logX, g_logX);
    cudaGetSymbolAddress((void**)&p_logP, g_logP);

    prep_b_kernel<<<(MATSZ * CDIM) / 256, 256>>>(A);
    osj_logm_kernel<<<CDIM, 256>>>(P, p_logP);
    compute_q_kernel<<<CDIM, 256>>>();
    osj_logm_kernel<<<NMAT, 256>>>(X, p_logX);
    gemm_kernel<<<NMAT / BM, 128>>>(p_logX, out);
}

// round 17
// speedup vs baseline: 6.7385x; 1.1231x over previous
#include <cuda_runtime.h>
#include <cstddef>

#define NMAT 32768
#define CDIM 128
#define NDIM 64
#define MATSZ 4096  // 64*64
#define GSTR 68     // column stride (floats): 16B-aligned rows, 272B stride

typedef unsigned long long ull;

// Packed f32x2 helpers (FFMA2/FMUL2 — only reachable via PTX)
__device__ __forceinline__ ull pk2(float lo, float hi) {
    ull r; asm("mov.b64 %0, {%1, %2};" : "=l"(r) : "f"(lo), "f"(hi)); return r;
}
__device__ __forceinline__ void upk2(ull v, float& lo, float& hi) {
    asm("mov.b64 {%0, %1}, %2;" : "=f"(lo), "=f"(hi) : "l"(v));
}
__device__ __forceinline__ ull fma2_(ull a, ull b, ull c) {
    ull d; asm("fma.rn.f32x2 %0, %1, %2, %3;"
               : "=l"(d) : "l"(a), "l"(b), "l"(c)); return d;
}
__device__ __forceinline__ ull mul2_(ull a, ull b) {
    ull d; asm("mul.rn.f32x2 %0, %1, %2;" : "=l"(d) : "l"(a), "l"(b)); return d;
}

// Scratch (static device arrays: the sanctioned alloc-free workaround)
__device__ float g_logX[(size_t)NMAT * MATSZ];   // 512 MB
__device__ float g_logP[CDIM * MATSZ];           // 2 MB
__device__ float g_B[MATSZ * CDIM];              // A_sym, k-major for GEMM (2 MB)
__device__ float g_q[CDIM];                      // tr(logP_c * A_sym_c)

// ---------------------------------------------------------------------------
// Build B[k][c] = A_sym_c[i][j], k = i*64+j, where A_sym = tril(A,-1)+tril^T+diag
// ---------------------------------------------------------------------------
__global__ void prep_b_kernel(const float* __restrict__ A) {
    int lin = blockIdx.x * blockDim.x + threadIdx.x;   // 0 .. 4096*128-1
    int c = lin & (CDIM - 1);
    int k = lin >> 7;
    int i = k >> 6, j = k & 63;
    float v;
    if (i == j)      v = A[(size_t)c * MATSZ + i * 64 + i];
    else if (i > j)  v = A[(size_t)c * MATSZ + i * 64 + j];
    else             v = A[(size_t)c * MATSZ + j * 64 + i];
    g_B[(size_t)k * CDIM + c] = v;
}

// ---------------------------------------------------------------------------
// One-sided Jacobi logm with XOR-quadruple scheduling + packed f32x2 math.
// One CTA (256 threads) per 64x64 SPD matrix.
// 1) LDLT factor X = W D^-1 W^T, scale columns by rsqrt(d): X = G G^T.
// 2) 63 rounds/sweep as 21 groups of 3 (masks {m1,m2,m1^m2}, GF(4)* cosets).
//    4-column cosets of {0,m1,m2,m3} closed under all 3 pairings; 16-thread
//    group keeps 4 columns (4 rows each, as 2 f32x2 regs) in registers across
//    the 3 rounds. Branchless rotations (inactive -> exact identity, t=0),
//    fast-intrinsic params, incremental norms, store-skip on idle groups.
// 3) lambda_i = ||g_i||^2 (recomputed exactly), logm = sum w_i g_i g_i^T.
// ---------------------------------------------------------------------------
__global__ __launch_bounds__(256, 4) void osj_logm_kernel(
    const float* __restrict__ src, float* __restrict__ dst) {
    __shared__ float sG[64][GSTR];      // column-major: sG[col][row]
    __shared__ float snorm[64];         // tracked squared column norms
    __shared__ float sw[64];            // log(lam)/lam weights
    __shared__ unsigned char spow[64];  // GF(64)* powers of x
    __shared__ unsigned char sreps[21][16]; // coset reps per group
    __shared__ int sAny;

    const int tid  = threadIdx.x;
    const int lane = tid & 31;
    const int w    = tid >> 5;
    const float* Xm = src + (size_t)blockIdx.x * MATSZ;

    // GF(64) power table: x^6 = x + 1 (primitive poly 0x43)
    if (tid == 0) {
        unsigned v = 1;
        for (int i = 0; i < 63; i++) {
            spow[i] = (unsigned char)v;
            v <<= 1;
            if (v & 64) v ^= 0x43;
        }
    }
    // Load X, zeroing the strict upper part of each column (r < c)
    #pragma unroll
    for (int t = 0; t < 16; t++) {
        int idx = tid + t * 256;
        int c = idx >> 6, r = idx & 63;
        sG[c][r] = (r < c) ? 0.0f : Xm[idx];
    }
    __syncthreads();

    // Coset-representative table (uses spow; consumed only after many barriers)
    for (int grp = w; grp < 21; grp += 8) {
        int m1 = spow[grp], m2 = spow[grp + 21], m3 = m1 ^ m2;
        int cnt = 0;
        #pragma unroll
        for (int h = 0; h < 2; h++) {
            int x = lane + 32 * h;
            bool rep = (x < (x ^ m1)) && (x < (x ^ m2)) && (x < (x ^ m3));
            unsigned bb = __ballot_sync(0xffffffffu, rep);
            if (rep)
                sreps[grp][cnt + __popc(bb & ((1u << lane) - 1u))] =
                    (unsigned char)x;
            cnt += __popc(bb);
        }
    }

    // LDLT (right-looking, unscaled W = L*D in lower triangle), 1 barrier/step
    for (int j = 0; j < 64; j++) {
        float recip = __frcp_rn(sG[j][j]);
        for (int c = j + 1 + (tid >> 3); c < 64; c += 32) {
            float wjc = sG[j][c] * recip;
            #pragma unroll 4
            for (int r = c + (tid & 7); r < 64; r += 8)
                sG[c][r] -= sG[j][r] * wjc;
        }
        __syncthreads();
    }
    // Scale columns: G[:,j] = W[:,j] * rsqrt(d_j); fused initial norms.
    {
        int col = tid >> 2, s4 = tid & 3;
        float s = rsqrtf(sG[col][col]);
        __syncwarp();
        float acc = 0.0f;
        #pragma unroll
        for (int k = 0; k < 16; k++) {
            int r = s4 + 4 * k;
            float v = sG[col][r] * s;
            sG[col][r] = v;
            acc += v * v;
        }
        acc += __shfl_xor_sync(0xffffffffu, acc, 1);
        acc += __shfl_xor_sync(0xffffffffu, acc, 2);
        if (s4 == 0) snorm[col] = acc;
    }
    __syncthreads();

    const float eps2 = 4e-12f;   // (2e-6)^2 relative rotation threshold
    const int ci  = tid >> 4;    // coset index 0..15
    const int sub = tid & 15;    // sub-thread: owns rows 4*sub..4*sub+3

    for (int sweep = 0; sweep < 14; sweep++) {
        if (tid == 0) sAny = 0;
        __syncthreads();
        for (int grp = 0; grp < 21; grp++) {
            const int m1 = spow[grp], m2 = spow[grp + 21], m3 = m1 ^ m2;
            const int c0 = sreps[grp][ci];
            const int c1 = c0 ^ m1, c2 = c0 ^ m2, c3 = c0 ^ m3;
            // Load 4 columns (4 rows each) as packed f32x2 pairs + norms
            ull G[4][2];
            {
                ulonglong2 u;
                u = *(const ulonglong2*)&sG[c0][4 * sub];
                G[0][0] = u.x; G[0][1] = u.y;
                u = *(const ulonglong2*)&sG[c1][4 * sub];
                G[1][0] = u.x; G[1][1] = u.y;
                u = *(const ulonglong2*)&sG[c2][4 * sub];
                G[2][0] = u.x; G[2][1] = u.y;
                u = *(const ulonglong2*)&sG[c3][4 * sub];
                G[3][0] = u.x; G[3][1] = u.y;
            }
            float n[4] = { snorm[c0], snorm[c1], snorm[c2], snorm[c3] };
            bool anyv = false;

            // 6 rotations: rounds m1:(01)(23)  m2:(02)(13)  m3:(03)(12)
            // Branchless: inactive -> t=0 -> cc=1, sn=0 (exact identity).
            #pragma unroll
            for (int rr = 0; rr < 3; rr++) {
                #pragma unroll
                for (int h = 0; h < 2; h++) {
                    int x, y;
                    if (rr == 0) { x = h ? 2 : 0; y = h ? 3 : 1; }
                    else if (rr == 1) { x = h ? 1 : 0; y = h ? 3 : 2; }
                    else { x = h ? 1 : 0; y = h ? 2 : 3; }
                    float dlo, dhi;
                    upk2(fma2_(G[x][0], G[y][0], mul2_(G[x][1], G[y][1])),
                         dlo, dhi);
                    float dpq = dlo + dhi;
                    dpq += __shfl_xor_sync(0xffffffffu, dpq, 1);
                    dpq += __shfl_xor_sync(0xffffffffu, dpq, 2);
                    dpq += __shfl_xor_sync(0xffffffffu, dpq, 4);
                    dpq += __shfl_xor_sync(0xffffffffu, dpq, 8);
                    bool active = (dpq * dpq > eps2 * n[x] * n[y]);
                    float dsafe = active ? dpq : 1.0f;
                    float tau = __fdividef(n[y] - n[x], 2.0f * dsafe);
                    float tt = fmaf(tau, tau, 1.0f);
                    float sq = tt * rsqrtf(tt);              // sqrt(1+tau^2)
                    float t = copysignf(__fdividef(1.0f, fabsf(tau) + sq), tau);
                    t = active ? t : 0.0f;
                    float cc = rsqrtf(fmaf(t, t, 1.0f));     // t=0 -> exactly 1
                    float sn = t * cc;
                    ull cc2 = pk2(cc, cc);
                    ull sn2 = pk2(sn, sn);
                    ull ns2 = pk2(-sn, -sn);
                    ull a0 = G[x][0], a1 = G[x][1];
                    ull b0 = G[y][0], b1 = G[y][1];
                    G[x][0] = fma2_(cc2, a0, mul2_(ns2, b0));
                    G[x][1] = fma2_(cc2, a1, mul2_(ns2, b1));
                    G[y][0] = fma2_(sn2, a0, mul2_(cc2, b0));
                    G[y][1] = fma2_(sn2, a1, mul2_(cc2, b1));
                    float tdpq = t * dpq;
                    n[x] -= tdpq;
                    n[y] += tdpq;
                    anyv |= active;
                }
            }
            if (anyv) {
                *(ulonglong2*)&sG[c0][4 * sub] =
                    make_ulonglong2(G[0][0], G[0][1]);
                *(ulonglong2*)&sG[c1][4 * sub] =
                    make_ulonglong2(G[1][0], G[1][1]);
                *(ulonglong2*)&sG[c2][4 * sub] =
                    make_ulonglong2(G[2][0], G[2][1]);
                *(ulonglong2*)&sG[c3][4 * sub] =
                    make_ulonglong2(G[3][0], G[3][1]);
                if (sub == 0) {
                    snorm[c0] = n[0]; snorm[c1] = n[1];
                    snorm[c2] = n[2]; snorm[c3] = n[3];
                    sAny = 1;
                }
            }
            __syncthreads();
        }
        int anyAll = sAny;
        __syncthreads();
        if (!anyAll) break;
    }

    // Exact column norms -> weights w = log(lam)/lam  (float4 loads)
    {
        int col = tid >> 2, s4 = tid & 3;
        float acc = 0.0f;
        #pragma unroll
        for (int k = 0; k < 4; k++) {
            float4 v = *(const float4*)&sG[col][s4 * 16 + 4 * k];
            acc += v.x * v.x + v.y * v.y + v.z * v.z + v.w * v.w;
        }
        acc += __shfl_xor_sync(0xffffffffu, acc, 1);
        acc += __shfl_xor_sync(0xffffffffu, acc, 2);
        if (s4 == 0) {
            float lam = fmaxf(acc, 1e-12f);
            sw[col] = logf(lam) / lam;
        }
    }
    __syncthreads();

    // logm[i][j] = sum_k w_k * sG[k][i] * sG[k][j], 4x4 tile, packed f32x2
    {
        int i0 = (tid >> 4) << 2;
        int j0 = (tid & 15) << 2;
        ull acc2[4][2];
        #pragma unroll
        for (int i = 0; i < 4; i++) { acc2[i][0] = 0ull; acc2[i][1] = 0ull; }
        for (int k = 0; k < 64; k++) {
            float wk = sw[k];
            float4 ra = *(const float4*)&sG[k][i0];
            ulonglong2 rbp = *(const ulonglong2*)&sG[k][j0];
            ull w2 = pk2(wk, wk);
            ull rb01 = mul2_(rbp.x, w2);
            ull rb23 = mul2_(rbp.y, w2);
            ull r0 = pk2(ra.x, ra.x);
            ull r1 = pk2(ra.y, ra.y);
            ull r2 = pk2(ra.z, ra.z);
            ull r3 = pk2(ra.w, ra.w);
            acc2[0][0] = fma2_(r0, rb01, acc2[0][0]);
            acc2[0][1] = fma2_(r0, rb23, acc2[0][1]);
            acc2[1][0] = fma2_(r1, rb01, acc2[1][0]);
            acc2[1][1] = fma2_(r1, rb23, acc2[1][1]);
            acc2[2][0] = fma2_(r2, rb01, acc2[2][0]);
            acc2[2][1] = fma2_(r2, rb23, acc2[2][1]);
            acc2[3][0] = fma2_(r3, rb01, acc2[3][0]);
            acc2[3][1] = fma2_(r3, rb23, acc2[3][1]);
        }
        float* out = dst + (size_t)blockIdx.x * MATSZ;
        #pragma unroll
        for (int i = 0; i < 4; i++) {
            float4 v;
            upk2(acc2[i][0], v.x, v.y);
            upk2(acc2[i][1], v.z, v.w);
            *(float4*)(out + (i0 + i) * 64 + j0) = v;
        }
    }
}

// ---------------------------------------------------------------------------
// q[c] = tr(logP_c * A_sym_c) = sum_k logP[c][k] * B[k][c]
// ---------------------------------------------------------------------------
__global__ void compute_q_kernel() {
    int c = blockIdx.x;
    int tid = threadIdx.x;
    __shared__ float sred[256];
    float acc = 0.0f;
    for (int k = tid; k < MATSZ; k += 256)
        acc += g_logP[(size_t)c * MATSZ + k] * g_B[(size_t)k * CDIM + c];
    sred[tid] = acc;
    __syncthreads();
    for (int o = 128; o > 0; o >>= 1) {
        if (tid < o) sred[tid] += sred[tid + o];
        __syncthreads();
    }
    if (tid == 0) g_q[c] = sred[0];
}

// ---------------------------------------------------------------------------
// SGEMM: out[M x 128] = logX[M x 4096] @ B[4096 x 128] - q[c]
// BM=64, BN=128, BK=16, TM=TN=8, 128 threads.
// ---------------------------------------------------------------------------
#define BM 64
#define BN 128
#define BK 16
__global__ __launch_bounds__(128) void gemm_kernel(
    const float* __restrict__ Amat, float* __restrict__ out) {
    __shared__ float As[BK][BM];   // transposed A tile
    __shared__ float Bs[BK][BN];
    __shared__ float sqv[BN];

    int tid = threadIdx.x;
    int rowg = tid >> 4;    // 0..7
    int colg = tid & 15;    // 0..15
    size_t row0 = (size_t)blockIdx.x * BM;

    if (tid < BN) sqv[tid] = g_q[tid];

    float acc[8][8];
    #pragma unroll
    for (int i = 0; i < 8; i++)
        #pragma unroll
        for (int j = 0; j < 8; j++) acc[i][j] = 0.0f;

    for (int kt = 0; kt < MATSZ; kt += BK) {
        #pragma unroll
        for (int l = 0; l < 2; l++) {
            int lin = tid + l * 128;
            int r = lin >> 2;
            int k4 = (lin & 3) * 4;
            float4 v = *(const float4*)(Amat + (row0 + r) * MATSZ + kt + k4);
            As[k4 + 0][r] = v.x; As[k4 + 1][r] = v.y;
            As[k4 + 2][r] = v.z; As[k4 + 3][r] = v.w;
        }
        #pragma unroll
        for (int l = 0; l < 4; l++) {
            int lin = tid + l * 128;
            int r = lin >> 5;
            int c4 = (lin & 31) * 4;
            *(float4*)&Bs[r][c4] =
                *(const float4*)(g_B + (size_t)(kt + r) * CDIM + c4);
        }
        __syncthreads();
        #pragma unroll
        for (int k = 0; k < BK; k++) {
            float ra[8], rb[8];
            #pragma unroll
            for (int i = 0; i < 8; i++) ra[i] = As[k][rowg * 8 + i];
            #pragma unroll
            for (int j = 0; j < 8; j++) rb[j] = Bs[k][colg * 8 + j];
            #pragma unroll
            for (int i = 0; i < 8; i++)
                #pragma unroll
                for (int j = 0; j < 8; j++)
                    acc[i][j] += ra[i] * rb[j];
        }
        __syncthreads();
    }
    #pragma unroll
    for (int i = 0; i < 8; i++) {
        size_t rr = row0 + rowg * 8 + i;
        #pragma unroll
        for (int j = 0; j < 8; j++) {
            int cc = colg * 8 + j;
            out[rr * CDIM + cc] = acc[i][j] - sqv[cc];
        }
    }
}

// ---------------------------------------------------------------------------
extern "C" void kernel_launch(void* const* d_in, const int* in_sizes, int n_in,
                              void* d_out, int out_size) {
    const float* X = (const float*)d_in[0];   // (32768, 64, 64)
    const float* P = (const float*)d_in[1];   // (128, 64, 64)
    const float* A = (const float*)d_in[2];   // (128, 64, 64)
    float* out = (float*)d_out;               // (32768, 128)

    float *p_logX, *p_logP;
    cudaGetSymbolAddress((void**)&p_logX, g_logX);
    cudaGetSymbolAddress((void**)&p_logP, g_logP);

    prep_b_kernel<<<(MATSZ * CDIM) / 256, 256>>>(A);
    osj_logm_kernel<<<CDIM, 256>>>(P, p_logP);
    compute_q_kernel<<<CDIM, 256>>>();
    osj_logm_kernel<<<NMAT, 256>>>(X, p_logX);
    gemm_kernel<<<NMAT / BM, 128>>>(p_logX, out);
}